// round 3
// baseline (speedup 1.0000x reference)
#include <cuda_runtime.h>
#include <cstdint>

#define DEV_INLINE __device__ __forceinline__

// ---------------- problem constants ----------------
constexpr int NN   = 100000;   // nodes
constexpr int NE   = 300000;   // edges
constexpr int D    = 256;      // feature dim
constexpr int HID2 = 512;      // 2*D (GIN MLP hidden)
constexpr int NHID = 512;      // proj hidden
constexpr int NOUT = 768;      // output dim
constexpr int NG   = 4096;     // graphs
constexpr int LGIN = 4;        // GIN layers

// ---------------- scratch (device globals; no cudaMalloc allowed) ----------------
__device__ float g_agg [(size_t)NN * D];     // (1+eps)*h + neighbor sum
__device__ float g_h   [(size_t)NN * D];     // layer output features
__device__ float g_t   [(size_t)NN * HID2];  // GIN MLP hidden
__device__ float g_pool[(size_t)NG * D];     // pooled sums
__device__ float g_cnt [NG];                 // per-graph node counts
__device__ float g_p1  [(size_t)NG * NHID];  // head hidden
__device__ float g_bns [5 * D];              // BN scale  = gamma * rsqrt(var+eps)
__device__ float g_bnb [5 * D];              // BN shift  = beta - mean*scale
__device__ int   g_is64;                     // 1 if index tensors are int64

// ---------------- helpers ----------------
DEV_INLINE void red_add_v4(float* p, float4 v) {
    asm volatile("red.global.add.v4.f32 [%0], {%1, %2, %3, %4};"
                 :: "l"(p), "f"(v.x), "f"(v.y), "f"(v.z), "f"(v.w) : "memory");
}

DEV_INLINE long long load_index(const void* base, long long i, int is64) {
    if (is64) return ((const long long*)base)[i];
    return (long long)((const int*)base)[i];
}

// Detect whether edge_index is int64 (every hi 32-bit word zero for values < 2^31)
// or int32 (hi-word slots hold actual node ids, ~never all zero across 256 samples).
__global__ void detect_idx(const unsigned int* __restrict__ w) {
    unsigned int nz = 0;
    #pragma unroll 1
    for (int k = 0; k < 256; k++) nz |= w[2 * k + 1];
    g_is64 = (nz == 0u) ? 1 : 0;
}

// Precompute BN eval-mode scale/shift for all 5 BN parameter sets.
__global__ void bn_precompute(const float* __restrict__ gamma, const float* __restrict__ beta,
                              const float* __restrict__ mean,  const float* __restrict__ var) {
    int i = blockIdx.x * blockDim.x + threadIdx.x;
    if (i < 5 * D) {
        float s = gamma[i] * rsqrtf(var[i] + 1e-5f);
        g_bns[i] = s;
        g_bnb[i] = beta[i] - mean[i] * s;
    }
}

// agg = (1 + eps[l]) * h   (fused self-term + init, vectorized)
__global__ void init_agg(float* __restrict__ agg, const float* __restrict__ hin,
                         const float* __restrict__ eps_arr, int l) {
    size_t i = (size_t)blockIdx.x * blockDim.x + threadIdx.x;
    if (i < (size_t)NN * D / 4) {
        float s = 1.0f + __ldg(&eps_arr[l]);
        float4 v = ((const float4*)hin)[i];
        v.x *= s; v.y *= s; v.z *= s; v.w *= s;
        ((float4*)agg)[i] = v;
    }
}

// agg[dst] += h[src]   one warp per edge, 2x red.v4 per lane (256 floats/row)
__global__ void scatter_edges(float* __restrict__ agg, const float* __restrict__ h,
                              const void* __restrict__ ei) {
    int wid = (int)(((size_t)blockIdx.x * blockDim.x + threadIdx.x) >> 5);
    if (wid >= NE) return;
    int lane = threadIdx.x & 31;
    int is64 = g_is64;
    long long s = load_index(ei, wid, is64);
    long long d = load_index(ei, (long long)NE + wid, is64);
    const float4* hs = (const float4*)(h + (size_t)s * D);
    float*        ad = agg + (size_t)d * D;
    float4 v0 = __ldg(hs + lane);
    float4 v1 = __ldg(hs + 32 + lane);
    red_add_v4(ad + lane * 4,       v0);
    red_add_v4(ad + 128 + lane * 4, v1);
}

// pooled[batch[n]] += h[n]; cnt[batch[n]] += 1   one warp per node
__global__ void pool_scatter(float* __restrict__ pool, float* __restrict__ cnt,
                             const float* __restrict__ h, const void* __restrict__ batch) {
    int wid = (int)(((size_t)blockIdx.x * blockDim.x + threadIdx.x) >> 5);
    if (wid >= NN) return;
    int lane = threadIdx.x & 31;
    long long g = load_index(batch, wid, g_is64);
    const float4* hs = (const float4*)(h + (size_t)wid * D);
    float*        pd = pool + (size_t)g * D;
    float4 v0 = __ldg(hs + lane);
    float4 v1 = __ldg(hs + 32 + lane);
    red_add_v4(pd + lane * 4,       v0);
    red_add_v4(pd + 128 + lane * 4, v1);
    if (lane == 0) atomicAdd(&cnt[g], 1.0f);
}

__global__ void zero_pool(float* __restrict__ pool, float* __restrict__ cnt) {
    int i = blockIdx.x * blockDim.x + threadIdx.x;
    if (i < NG * D / 4) ((float4*)pool)[i] = make_float4(0.f, 0.f, 0.f, 0.f);
    if (i < NG) cnt[i] = 0.f;
}

__global__ void normalize_pool(float* __restrict__ pool, const float* __restrict__ cnt) {
    int i = blockIdx.x * blockDim.x + threadIdx.x;
    if (i < NG * D / 4) {
        int g = i >> 6;                       // 64 float4 per row
        float s = 1.0f / fmaxf(__ldg(&cnt[g]), 1.0f);
        float4 v = ((float4*)pool)[i];
        v.x *= s; v.y *= s; v.z *= s; v.w *= s;
        ((float4*)pool)[i] = v;
    }
}

// ---------------- fp32 SGEMM: C = epi(A[M,K] @ B[K,N] + bias) ----------------
// EPI: 0 = bias, 1 = bias+relu, 2 = bias+relu+BN(scale,shift)
// 128x128 block tile, BK=8, 256 threads, 8x8 per thread, double-buffered smem.
// Warp layout 4x2 (32x64 per warp), lanes 4x8 -> 384B unique smem/warp/k (compute-bound).
template<int EPI>
__global__ __launch_bounds__(256)
void sgemm(const float* __restrict__ A, const float* __restrict__ B,
           const float* __restrict__ bias, float* __restrict__ C,
           int M, int N, int K,
           const float* __restrict__ bns, const float* __restrict__ bnb)
{
    constexpr int BM = 128, BN = 128, BK = 8;
    __shared__ float As[2][BK][BM + 4];   // pad to 132 -> conflict-free transposed stores
    __shared__ float Bs[2][BK][BN];

    const int tid  = threadIdx.x;
    const int row0 = blockIdx.y * BM;
    const int col0 = blockIdx.x * BN;

    // global-load mapping
    const int arow = tid >> 1;            // 0..127
    const int acol = (tid & 1) << 2;      // 0 or 4
    const int brow = tid >> 5;            // 0..7
    const int bcol = (tid & 31) << 2;     // 0..124

    // compute mapping: 8 warps as 4(rows) x 2(cols); lanes 4x8
    const int w    = tid >> 5;
    const int lane = tid & 31;
    const int rowt = (w & 3) * 32 + (lane >> 3) * 8;
    const int colt = (w >> 2) * 64 + (lane & 7) * 8;

    const bool arow_ok = (row0 + arow) < M;
    const float* Ap = A + (size_t)(row0 + arow) * K + acol;
    const float* Bp = B + (size_t)brow * N + col0 + bcol;

    float acc[8][8];
    #pragma unroll
    for (int i = 0; i < 8; i++)
        #pragma unroll
        for (int j = 0; j < 8; j++) acc[i][j] = 0.f;

    // prologue: stage 0
    {
        float4 av = arow_ok ? *(const float4*)Ap : make_float4(0.f, 0.f, 0.f, 0.f);
        As[0][acol + 0][arow] = av.x;
        As[0][acol + 1][arow] = av.y;
        As[0][acol + 2][arow] = av.z;
        As[0][acol + 3][arow] = av.w;
        *(float4*)&Bs[0][brow][bcol] = *(const float4*)Bp;
    }
    __syncthreads();

    const int nk = K >> 3;
    for (int kt = 0; kt < nk; kt++) {
        const int cur = kt & 1;
        float4 av = make_float4(0.f, 0.f, 0.f, 0.f);
        float4 bv = make_float4(0.f, 0.f, 0.f, 0.f);
        const bool has_next = (kt + 1) < nk;
        if (has_next) {
            if (arow_ok) av = *(const float4*)(Ap + (kt + 1) * BK);
            bv = *(const float4*)(Bp + (size_t)(kt + 1) * BK * N);
        }
        #pragma unroll
        for (int k = 0; k < BK; k++) {
            float ar[8], br[8];
            *(float4*)&ar[0] = *(const float4*)&As[cur][k][rowt];
            *(float4*)&ar[4] = *(const float4*)&As[cur][k][rowt + 4];
            *(float4*)&br[0] = *(const float4*)&Bs[cur][k][colt];
            *(float4*)&br[4] = *(const float4*)&Bs[cur][k][colt + 4];
            #pragma unroll
            for (int i = 0; i < 8; i++)
                #pragma unroll
                for (int j = 0; j < 8; j++)
                    acc[i][j] = fmaf(ar[i], br[j], acc[i][j]);
        }
        if (has_next) {
            const int nxt = cur ^ 1;
            As[nxt][acol + 0][arow] = av.x;
            As[nxt][acol + 1][arow] = av.y;
            As[nxt][acol + 2][arow] = av.z;
            As[nxt][acol + 3][arow] = av.w;
            *(float4*)&Bs[nxt][brow][bcol] = bv;
            __syncthreads();
        }
    }

    // epilogue
    float bias8[8], s8[8], t8[8];
    #pragma unroll
    for (int j = 0; j < 8; j++) {
        int c = col0 + colt + j;
        bias8[j] = __ldg(&bias[c]);
        if (EPI == 2) { s8[j] = __ldg(&bns[c]); t8[j] = __ldg(&bnb[c]); }
    }
    #pragma unroll
    for (int i = 0; i < 8; i++) {
        int r = row0 + rowt + i;
        if (r < M) {
            float* Cp = C + (size_t)r * N + col0 + colt;
            float o[8];
            #pragma unroll
            for (int j = 0; j < 8; j++) {
                float v = acc[i][j] + bias8[j];
                if (EPI >= 1) v = fmaxf(v, 0.f);
                if (EPI == 2) v = fmaf(v, s8[j], t8[j]);
                o[j] = v;
            }
            *(float4*)(Cp)     = *(float4*)&o[0];
            *(float4*)(Cp + 4) = *(float4*)&o[4];
        }
    }
}

// ---------------- launcher ----------------
extern "C" void kernel_launch(void* const* d_in, const int* in_sizes, int n_in,
                              void* d_out, int out_size)
{
    const float* x     = (const float*)d_in[0];
    const void*  ei    = d_in[1];
    const void*  batch = d_in[2];
    const float* w1    = (const float*)d_in[3];
    const float* b1    = (const float*)d_in[4];
    const float* w2    = (const float*)d_in[5];
    const float* b2    = (const float*)d_in[6];
    const float* eps   = (const float*)d_in[7];
    const float* bng   = (const float*)d_in[8];
    const float* bnbt  = (const float*)d_in[9];
    const float* bnm   = (const float*)d_in[10];
    const float* bnv   = (const float*)d_in[11];
    const float* wp1   = (const float*)d_in[12];
    const float* bp1   = (const float*)d_in[13];
    const float* wp2   = (const float*)d_in[14];
    const float* bp2   = (const float*)d_in[15];
    float* out = (float*)d_out;

    float *agg, *h, *t, *pool, *cnt, *p1, *bns, *bnb;
    cudaGetSymbolAddress((void**)&agg,  g_agg);
    cudaGetSymbolAddress((void**)&h,    g_h);
    cudaGetSymbolAddress((void**)&t,    g_t);
    cudaGetSymbolAddress((void**)&pool, g_pool);
    cudaGetSymbolAddress((void**)&cnt,  g_cnt);
    cudaGetSymbolAddress((void**)&p1,   g_p1);
    cudaGetSymbolAddress((void**)&bns,  g_bns);
    cudaGetSymbolAddress((void**)&bnb,  g_bnb);

    detect_idx<<<1, 1>>>((const unsigned int*)ei);
    bn_precompute<<<(5 * D + 255) / 256, 256>>>(bng, bnbt, bnm, bnv);

    const int bnidx[4] = {0, 0, 1, 2};   // reference's bn-index bug, kept

    const int elem_blocks    = (NN * D / 4 + 255) / 256;       // 25000
    const int edge_blocks    = (int)(((size_t)NE * 32 + 255) / 256);  // 37500
    const int node_blocks    = (int)(((size_t)NN * 32 + 255) / 256);  // 12500
    const int poolv4_blocks  = (NG * D / 4 + 255) / 256;       // 1024

    for (int l = 0; l < LGIN; l++) {
        const float* hin = (l == 0) ? x : h;
        init_agg<<<elem_blocks, 256>>>(agg, hin, eps, l);
        scatter_edges<<<edge_blocks, 256>>>(agg, hin, ei);
        // t = relu(agg @ W1 + b1)   [NN, 512]
        sgemm<1><<<dim3(HID2 / 128, (NN + 127) / 128), 256>>>(
            agg, w1 + (size_t)l * D * HID2, b1 + (size_t)l * HID2, t,
            NN, HID2, D, nullptr, nullptr);
        // h = BN(relu(t @ W2 + b2)) [NN, 256]
        sgemm<2><<<dim3(D / 128, (NN + 127) / 128), 256>>>(
            t, w2 + (size_t)l * HID2 * D, b2 + (size_t)l * D, h,
            NN, D, HID2, bns + bnidx[l] * D, bnb + bnidx[l] * D);
    }

    zero_pool<<<poolv4_blocks, 256>>>(pool, cnt);
    pool_scatter<<<node_blocks, 256>>>(pool, cnt, h, batch);
    normalize_pool<<<poolv4_blocks, 256>>>(pool, cnt);

    // p1 = relu(pool @ Wp1 + bp1)  [NG, 512]
    sgemm<1><<<dim3(NHID / 128, NG / 128), 256>>>(
        pool, wp1, bp1, p1, NG, NHID, D, nullptr, nullptr);
    // out = p1 @ Wp2 + bp2         [NG, 768]
    sgemm<0><<<dim3(NOUT / 128, NG / 128), 256>>>(
        p1, wp2, bp2, out, NG, NOUT, NHID, nullptr, nullptr);
}

// round 4
// speedup vs baseline: 1.4251x; 1.4251x over previous
#include <cuda_runtime.h>
#include <mma.h>
#include <cstdint>

using namespace nvcuda;

#define DEV_INLINE __device__ __forceinline__

// ---------------- problem constants ----------------
constexpr int NN   = 100000;   // nodes
constexpr int NE   = 300000;   // edges
constexpr int D    = 256;      // feature dim
constexpr int HID2 = 512;      // 2*D (GIN MLP hidden)
constexpr int NHID = 512;      // proj hidden
constexpr int NOUT = 768;      // output dim
constexpr int NG   = 4096;     // graphs
constexpr int LGIN = 4;        // GIN layers

// ---------------- scratch (device globals; no cudaMalloc allowed) ----------------
__device__ float g_agg [(size_t)NN * D];
__device__ float g_h   [(size_t)NN * D];
__device__ float g_t   [(size_t)NN * HID2];
__device__ float g_pool[(size_t)NG * D];
__device__ float g_cnt [NG];
__device__ float g_p1  [(size_t)NG * NHID];
__device__ float g_bns [5 * D];
__device__ float g_bnb [5 * D];
__device__ int   g_is64;

// ---------------- helpers ----------------
DEV_INLINE void red_add_v4(float* p, float4 v) {
    asm volatile("red.global.add.v4.f32 [%0], {%1, %2, %3, %4};"
                 :: "l"(p), "f"(v.x), "f"(v.y), "f"(v.z), "f"(v.w) : "memory");
}

DEV_INLINE long long load_index(const void* base, long long i, int is64) {
    if (is64) return ((const long long*)base)[i];
    return (long long)((const int*)base)[i];
}

DEV_INLINE void cp_async16(const void* smem_dst, const void* gmem_src) {
    uint32_t s = (uint32_t)__cvta_generic_to_shared(smem_dst);
    asm volatile("cp.async.cg.shared.global [%0], [%1], 16;" :: "r"(s), "l"(gmem_src));
}
DEV_INLINE void cp_async_commit() { asm volatile("cp.async.commit_group;"); }
DEV_INLINE void cp_async_wait0()  { asm volatile("cp.async.wait_group 0;"); }

__global__ void detect_idx(const unsigned int* __restrict__ w) {
    unsigned int nz = 0;
    #pragma unroll 1
    for (int k = 0; k < 256; k++) nz |= w[2 * k + 1];
    g_is64 = (nz == 0u) ? 1 : 0;
}

__global__ void bn_precompute(const float* __restrict__ gamma, const float* __restrict__ beta,
                              const float* __restrict__ mean,  const float* __restrict__ var) {
    int i = blockIdx.x * blockDim.x + threadIdx.x;
    if (i < 5 * D) {
        float s = gamma[i] * rsqrtf(var[i] + 1e-5f);
        g_bns[i] = s;
        g_bnb[i] = beta[i] - mean[i] * s;
    }
}

// agg = (1 + eps[0]) * x   (only needed for layer 0; later layers fused into GEMM2)
__global__ void init_agg(float* __restrict__ agg, const float* __restrict__ hin,
                         const float* __restrict__ eps_arr, int l) {
    size_t i = (size_t)blockIdx.x * blockDim.x + threadIdx.x;
    if (i < (size_t)NN * D / 4) {
        float s = 1.0f + __ldg(&eps_arr[l]);
        float4 v = ((const float4*)hin)[i];
        v.x *= s; v.y *= s; v.z *= s; v.w *= s;
        ((float4*)agg)[i] = v;
    }
}

// agg[dst] += h[src]   one warp per edge (DRAM-bound, ~roofline already)
__global__ void scatter_edges(float* __restrict__ agg, const float* __restrict__ h,
                              const void* __restrict__ ei) {
    int wid = (int)(((size_t)blockIdx.x * blockDim.x + threadIdx.x) >> 5);
    if (wid >= NE) return;
    int lane = threadIdx.x & 31;
    int is64 = g_is64;
    long long s = load_index(ei, wid, is64);
    long long d = load_index(ei, (long long)NE + wid, is64);
    const float4* hs = (const float4*)(h + (size_t)s * D);
    float*        ad = agg + (size_t)d * D;
    float4 v0 = __ldg(hs + lane);
    float4 v1 = __ldg(hs + 32 + lane);
    red_add_v4(ad + lane * 4,       v0);
    red_add_v4(ad + 128 + lane * 4, v1);
}

__global__ void pool_scatter(float* __restrict__ pool, float* __restrict__ cnt,
                             const float* __restrict__ h, const void* __restrict__ batch) {
    int wid = (int)(((size_t)blockIdx.x * blockDim.x + threadIdx.x) >> 5);
    if (wid >= NN) return;
    int lane = threadIdx.x & 31;
    long long g = load_index(batch, wid, g_is64);
    const float4* hs = (const float4*)(h + (size_t)wid * D);
    float*        pd = pool + (size_t)g * D;
    float4 v0 = __ldg(hs + lane);
    float4 v1 = __ldg(hs + 32 + lane);
    red_add_v4(pd + lane * 4,       v0);
    red_add_v4(pd + 128 + lane * 4, v1);
    if (lane == 0) atomicAdd(&cnt[g], 1.0f);
}

__global__ void zero_pool(float* __restrict__ pool, float* __restrict__ cnt) {
    int i = blockIdx.x * blockDim.x + threadIdx.x;
    if (i < NG * D / 4) ((float4*)pool)[i] = make_float4(0.f, 0.f, 0.f, 0.f);
    if (i < NG) cnt[i] = 0.f;
}

__global__ void normalize_pool(float* __restrict__ pool, const float* __restrict__ cnt) {
    int i = blockIdx.x * blockDim.x + threadIdx.x;
    if (i < NG * D / 4) {
        int g = i >> 6;
        float s = 1.0f / fmaxf(__ldg(&cnt[g]), 1.0f);
        float4 v = ((float4*)pool)[i];
        v.x *= s; v.y *= s; v.z *= s; v.w *= s;
        ((float4*)pool)[i] = v;
    }
}

// ---------------- tf32 tensor-core GEMM: C = epi(A[M,K] @ B[K,N] + bias) ----------------
// EPI: 0=bias, 1=bias+relu, 2=bias+relu+BN(scale,shift)
// WAGG: epilogue additionally writes aggout = (1+eps[eps_idx]) * result  (N must equal D)
// Tiles: 128x128x16, 8 warps (2x4), warp tile 64x32 of m16n16k8 wmma frags.
// A staged col-major in smem (stride 136 -> conflict-free frag loads, addr=8k+m),
// B staged row-major via cp.async (stride 136 -> conflict-free, addr=8k+n).
template<int EPI, bool WAGG>
__global__ __launch_bounds__(256, 2)
void tgemm(const float* __restrict__ A, const float* __restrict__ B,
           const float* __restrict__ bias, float* __restrict__ C,
           int M, int N, int K,
           const float* __restrict__ bns, const float* __restrict__ bnb,
           float* __restrict__ aggout, const float* __restrict__ eps_arr, int eps_idx)
{
    constexpr int BM = 128, BN = 128, BK = 16, SA = 136, SB = 136;
    __shared__ float As[2][BK][SA];      // As[k][m]  (A col-major)
    __shared__ float Bs[2][BK][SB];      // Bs[k][n]  (B row-major)
    __shared__ float epi_s[8][16][20];   // per-warp accumulator staging

    const int tid  = threadIdx.x;
    const int row0 = blockIdx.y * BM;
    const int col0 = blockIdx.x * BN;
    const int w    = tid >> 5, lane = tid & 31;
    const int wrow = w >> 2,   wcol = w & 3;       // 2 x 4 warp grid

    // A load mapping: float4 id f in {tid, tid+256}: r = f>>2 (0..127), k4 = (f&3)*4
    const int ar  = tid >> 2;                      // 0..63 (second half = +64)
    const int ak  = (tid & 3) * 4;
    const bool a0ok = (row0 + ar)      < M;
    const bool a1ok = (row0 + ar + 64) < M;
    const float* Ap0 = A + (size_t)(row0 + ar) * K + ak;
    const float* Ap1 = Ap0 + (size_t)64 * K;

    // B cp.async mapping: f: kr = f>>5 (0..15), c4 = (f&31)*4
    const int bk = tid >> 5;                       // 0..7 (second half = +8)
    const int bc = (tid & 31) * 4;
    const float* Bp0 = B + (size_t)bk * N + col0 + bc;
    const float* Bp1 = B + (size_t)(bk + 8) * N + col0 + bc;

    wmma::fragment<wmma::matrix_a, 16, 16, 8, wmma::precision::tf32, wmma::col_major> af[4];
    wmma::fragment<wmma::matrix_b, 16, 16, 8, wmma::precision::tf32, wmma::row_major> bf[2];
    wmma::fragment<wmma::accumulator, 16, 16, 8, float> cf[4][2];
    #pragma unroll
    for (int i = 0; i < 4; i++)
        #pragma unroll
        for (int j = 0; j < 2; j++) wmma::fill_fragment(cf[i][j], 0.0f);

    const float4 f4z = make_float4(0.f, 0.f, 0.f, 0.f);
    float4 a0 = a0ok ? *(const float4*)Ap0 : f4z;
    float4 a1 = a1ok ? *(const float4*)Ap1 : f4z;
    cp_async16(&Bs[0][bk][bc],     Bp0);
    cp_async16(&Bs[0][bk + 8][bc], Bp1);
    cp_async_commit();
    {   // STS A stage 0 (col-major scatter)
        As[0][ak + 0][ar] = a0.x; As[0][ak + 1][ar] = a0.y;
        As[0][ak + 2][ar] = a0.z; As[0][ak + 3][ar] = a0.w;
        As[0][ak + 0][ar + 64] = a1.x; As[0][ak + 1][ar + 64] = a1.y;
        As[0][ak + 2][ar + 64] = a1.z; As[0][ak + 3][ar + 64] = a1.w;
    }
    cp_async_wait0();
    __syncthreads();

    const int nk = K >> 4;
    for (int kt = 0; kt < nk; kt++) {
        const int cur = kt & 1, nxt = cur ^ 1;
        const bool hn = (kt + 1) < nk;
        if (hn) {
            a0 = a0ok ? *(const float4*)(Ap0 + (kt + 1) * BK) : f4z;
            a1 = a1ok ? *(const float4*)(Ap1 + (kt + 1) * BK) : f4z;
            cp_async16(&Bs[nxt][bk][bc],     Bp0 + (size_t)(kt + 1) * BK * N);
            cp_async16(&Bs[nxt][bk + 8][bc], Bp1 + (size_t)(kt + 1) * BK * N);
            cp_async_commit();
        }
        #pragma unroll
        for (int kk = 0; kk < 2; kk++) {
            #pragma unroll
            for (int i = 0; i < 4; i++) {
                wmma::load_matrix_sync(af[i], &As[cur][kk * 8][wrow * 64 + i * 16], SA);
                #pragma unroll
                for (int e = 0; e < af[i].num_elements; e++)
                    af[i].x[e] = wmma::__float_to_tf32(af[i].x[e]);
            }
            #pragma unroll
            for (int j = 0; j < 2; j++) {
                wmma::load_matrix_sync(bf[j], &Bs[cur][kk * 8][wcol * 32 + j * 16], SB);
                #pragma unroll
                for (int e = 0; e < bf[j].num_elements; e++)
                    bf[j].x[e] = wmma::__float_to_tf32(bf[j].x[e]);
            }
            #pragma unroll
            for (int i = 0; i < 4; i++)
                #pragma unroll
                for (int j = 0; j < 2; j++)
                    wmma::mma_sync(cf[i][j], af[i], bf[j], cf[i][j]);
        }
        if (hn) {
            As[nxt][ak + 0][ar] = a0.x; As[nxt][ak + 1][ar] = a0.y;
            As[nxt][ak + 2][ar] = a0.z; As[nxt][ak + 3][ar] = a0.w;
            As[nxt][ak + 0][ar + 64] = a1.x; As[nxt][ak + 1][ar + 64] = a1.y;
            As[nxt][ak + 2][ar + 64] = a1.z; As[nxt][ak + 3][ar + 64] = a1.w;
            cp_async_wait0();
        }
        __syncthreads();
    }

    // ---------------- epilogue ----------------
    float aggscale = 0.f;
    if (WAGG) aggscale = 1.0f + __ldg(&eps_arr[eps_idx]);
    const int er = lane & 15;            // row within 16
    const int ec = (lane >> 4) * 8;      // col segment: 0 or 8

    #pragma unroll
    for (int i = 0; i < 4; i++) {
        #pragma unroll
        for (int j = 0; j < 2; j++) {
            wmma::store_matrix_sync(&epi_s[w][0][0], cf[i][j], 20, wmma::mem_row_major);
            __syncwarp();
            const int rr = row0 + wrow * 64 + i * 16 + er;
            const int cc = col0 + wcol * 32 + j * 16 + ec;
            if (rr < M) {
                float4 v0 = *(const float4*)&epi_s[w][er][ec];
                float4 v1 = *(const float4*)&epi_s[w][er][ec + 4];
                float acc[8] = {v0.x, v0.y, v0.z, v0.w, v1.x, v1.y, v1.z, v1.w};
                float4 bb0 = *(const float4*)(bias + cc);
                float4 bb1 = *(const float4*)(bias + cc + 4);
                float bi[8] = {bb0.x, bb0.y, bb0.z, bb0.w, bb1.x, bb1.y, bb1.z, bb1.w};
                float s8[8], t8[8];
                if (EPI == 2) {
                    float4 s0 = *(const float4*)(bns + cc), s1 = *(const float4*)(bns + cc + 4);
                    float4 t0 = *(const float4*)(bnb + cc), t1 = *(const float4*)(bnb + cc + 4);
                    s8[0]=s0.x; s8[1]=s0.y; s8[2]=s0.z; s8[3]=s0.w;
                    s8[4]=s1.x; s8[5]=s1.y; s8[6]=s1.z; s8[7]=s1.w;
                    t8[0]=t0.x; t8[1]=t0.y; t8[2]=t0.z; t8[3]=t0.w;
                    t8[4]=t1.x; t8[5]=t1.y; t8[6]=t1.z; t8[7]=t1.w;
                }
                float o[8], g[8];
                #pragma unroll
                for (int e = 0; e < 8; e++) {
                    float v = acc[e] + bi[e];
                    if (EPI >= 1) v = fmaxf(v, 0.f);
                    if (EPI == 2) v = fmaf(v, s8[e], t8[e]);
                    o[e] = v;
                    if (WAGG) g[e] = v * aggscale;
                }
                float* Cp = C + (size_t)rr * N + cc;
                *(float4*)(Cp)     = *(const float4*)&o[0];
                *(float4*)(Cp + 4) = *(const float4*)&o[4];
                if (WAGG) {
                    float* Gp = aggout + (size_t)rr * N + cc;
                    *(float4*)(Gp)     = *(const float4*)&g[0];
                    *(float4*)(Gp + 4) = *(const float4*)&g[4];
                }
            }
            __syncwarp();
        }
    }
}

// ---------------- launcher ----------------
extern "C" void kernel_launch(void* const* d_in, const int* in_sizes, int n_in,
                              void* d_out, int out_size)
{
    const float* x     = (const float*)d_in[0];
    const void*  ei    = d_in[1];
    const void*  batch = d_in[2];
    const float* w1    = (const float*)d_in[3];
    const float* b1    = (const float*)d_in[4];
    const float* w2    = (const float*)d_in[5];
    const float* b2    = (const float*)d_in[6];
    const float* eps   = (const float*)d_in[7];
    const float* bng   = (const float*)d_in[8];
    const float* bnbt  = (const float*)d_in[9];
    const float* bnm   = (const float*)d_in[10];
    const float* bnv   = (const float*)d_in[11];
    const float* wp1   = (const float*)d_in[12];
    const float* bp1   = (const float*)d_in[13];
    const float* wp2   = (const float*)d_in[14];
    const float* bp2   = (const float*)d_in[15];
    float* out = (float*)d_out;

    float *agg, *h, *t, *pool, *cnt, *p1, *bns, *bnb;
    cudaGetSymbolAddress((void**)&agg,  g_agg);
    cudaGetSymbolAddress((void**)&h,    g_h);
    cudaGetSymbolAddress((void**)&t,    g_t);
    cudaGetSymbolAddress((void**)&pool, g_pool);
    cudaGetSymbolAddress((void**)&cnt,  g_cnt);
    cudaGetSymbolAddress((void**)&p1,   g_p1);
    cudaGetSymbolAddress((void**)&bns,  g_bns);
    cudaGetSymbolAddress((void**)&bnb,  g_bnb);

    detect_idx<<<1, 1>>>((const unsigned int*)ei);
    bn_precompute<<<(5 * D + 255) / 256, 256>>>(bng, bnbt, bnm, bnv);

    const int bnidx[4] = {0, 0, 1, 2};   // reference's bn-index bug, kept

    const int elem_blocks   = (NN * D / 4 + 255) / 256;
    const int edge_blocks   = (int)(((size_t)NE * 32 + 255) / 256);
    const int node_blocks   = (int)(((size_t)NN * 32 + 255) / 256);
    const int poolv4_blocks = (NG * D / 4 + 255) / 256;
    const int mrows = (NN + 127) / 128;   // 782

    init_agg<<<elem_blocks, 256>>>(agg, x, eps, 0);   // layer-0 self term

    for (int l = 0; l < LGIN; l++) {
        const float* hin = (l == 0) ? x : h;
        scatter_edges<<<edge_blocks, 256>>>(agg, hin, ei);
        // t = relu(agg @ W1 + b1)   [NN, 512]
        tgemm<1, false><<<dim3(HID2 / 128, mrows), 256>>>(
            agg, w1 + (size_t)l * D * HID2, b1 + (size_t)l * HID2, t,
            NN, HID2, D, nullptr, nullptr, nullptr, nullptr, 0);
        // h = BN(relu(t @ W2 + b2)) [NN, 256]; layers 0-2 also emit agg=(1+eps[l+1])*h
        if (l < LGIN - 1) {
            tgemm<2, true><<<dim3(D / 128, mrows), 256>>>(
                t, w2 + (size_t)l * HID2 * D, b2 + (size_t)l * D, h,
                NN, D, HID2, bns + bnidx[l] * D, bnb + bnidx[l] * D,
                agg, eps, l + 1);
        } else {
            tgemm<2, false><<<dim3(D / 128, mrows), 256>>>(
                t, w2 + (size_t)l * HID2 * D, b2 + (size_t)l * D, h,
                NN, D, HID2, bns + bnidx[l] * D, bnb + bnidx[l] * D,
                nullptr, nullptr, 0);
        }
    }

    zero_pool<<<poolv4_blocks, 256>>>(pool, cnt);
    pool_scatter<<<node_blocks, 256>>>(pool, cnt, h, batch);
    normalize_pool<<<poolv4_blocks, 256>>>(pool, cnt);

    // p1 = relu(pool @ Wp1 + bp1)  [NG, 512]
    tgemm<1, false><<<dim3(NHID / 128, NG / 128), 256>>>(
        pool, wp1, bp1, p1, NG, NHID, D, nullptr, nullptr, nullptr, nullptr, 0);
    // out = p1 @ Wp2 + bp2         [NG, 768]
    tgemm<0, false><<<dim3(NOUT / 128, NG / 128), 256>>>(
        p1, wp2, bp2, out, NG, NOUT, NHID, nullptr, nullptr, nullptr, nullptr, 0);
}

// round 6
// speedup vs baseline: 2.4952x; 1.7510x over previous
#include <cuda_runtime.h>
#include <cstdint>

#define DEV_INLINE __device__ __forceinline__

// ---------------- problem constants ----------------
constexpr int NN   = 100000;
constexpr int NE   = 300000;
constexpr int D    = 256;
constexpr int HID2 = 512;
constexpr int NHID = 512;
constexpr int NOUT = 768;
constexpr int NG   = 4096;
constexpr int LGIN = 4;

// ---------------- scratch (device globals) ----------------
__device__ float g_agg [(size_t)NN * D];
__device__ float g_h   [(size_t)NN * D];
__device__ float g_t   [(size_t)NN * HID2];
__device__ float g_pool[(size_t)NG * D];
__device__ float g_cnt [NG];
__device__ float g_p1  [(size_t)NG * NHID];
__device__ float g_bns [5 * D];
__device__ float g_bnb [5 * D];
__device__ int   g_is64;
// fragment-order tf32 weights (pre-permuted for mma.m16n8k8, cp.async-ready)
__device__ float g_wf1 [(size_t)LGIN * D * HID2];
__device__ float g_wf2 [(size_t)LGIN * HID2 * D];
__device__ float g_wfp1[(size_t)D * NHID];
__device__ float g_wfp2[(size_t)NHID * NOUT];

// ---------------- PTX helpers ----------------
DEV_INLINE void red_add_v4(float* p, float4 v) {
    asm volatile("red.global.add.v4.f32 [%0], {%1, %2, %3, %4};"
                 :: "l"(p), "f"(v.x), "f"(v.y), "f"(v.z), "f"(v.w) : "memory");
}
DEV_INLINE long long load_index(const void* base, long long i, int is64) {
    if (is64) return ((const long long*)base)[i];
    return (long long)((const int*)base)[i];
}
DEV_INLINE uint32_t smem_u32(const void* p) {
    uint32_t a;
    asm("{ .reg .u64 t; cvta.to.shared.u64 t, %1; cvt.u32.u64 %0, t; }" : "=r"(a) : "l"(p));
    return a;
}
DEV_INLINE void cp_async16s(uint32_t saddr, const void* g) {
    asm volatile("cp.async.cg.shared.global [%0], [%1], 16;" :: "r"(saddr), "l"(g) : "memory");
}
DEV_INLINE void cp_commit() { asm volatile("cp.async.commit_group;" ::: "memory"); }
template<int Nq> DEV_INLINE void cp_wait() { asm volatile("cp.async.wait_group %0;" :: "n"(Nq) : "memory"); }

DEV_INLINE uint32_t f2tf32(float f) {
    uint32_t r;
    asm("cvt.rna.tf32.f32 %0, %1;" : "=r"(r) : "f"(f));
    return r;
}
DEV_INLINE void mma_tf32(float4& c, uint32_t a0, uint32_t a1, uint32_t a2, uint32_t a3,
                         uint32_t b0, uint32_t b1) {
    asm volatile(
        "mma.sync.aligned.m16n8k8.row.col.f32.tf32.tf32.f32 "
        "{%0,%1,%2,%3}, {%4,%5,%6,%7}, {%8,%9}, {%0,%1,%2,%3};"
        : "+f"(c.x), "+f"(c.y), "+f"(c.z), "+f"(c.w)
        : "r"(a0), "r"(a1), "r"(a2), "r"(a3), "r"(b0), "r"(b1));
}

// ---------------- small kernels ----------------
__global__ void detect_idx(const unsigned int* __restrict__ w) {
    unsigned int nz = 0;
    #pragma unroll 1
    for (int k = 0; k < 256; k++) nz |= w[2 * k + 1];
    g_is64 = (nz == 0u) ? 1 : 0;
}

__global__ void bn_precompute(const float* __restrict__ gamma, const float* __restrict__ beta,
                              const float* __restrict__ mean,  const float* __restrict__ var) {
    int i = blockIdx.x * blockDim.x + threadIdx.x;
    if (i < 5 * D) {
        float s = gamma[i] * rsqrtf(var[i] + 1e-5f);
        g_bns[i] = s;
        g_bnb[i] = beta[i] - mean[i] * s;
    }
}

// Pre-permute weight [K][N] (row-major) into tf32 fragment order:
// id = ((nb*K16 + ks)*32 + nt)*128 + lane*4 + word
// value = tf32( w[ ks*16 + (lane&3) + word*4 ][ nb*256 + nt*8 + (lane>>2) ] )
__global__ void prep_w(const float* __restrict__ src, float* __restrict__ dst, int K, int N) {
    int id = blockIdx.x * blockDim.x + threadIdx.x;
    if (id >= K * N) return;
    int word = id & 3;
    int lane = (id >> 2) & 31;
    int nt   = (id >> 7) & 31;
    int blk  = id >> 12;
    int K16  = K >> 4;
    int ks   = blk % K16;
    int nb   = blk / K16;
    int n = nb * 256 + nt * 8 + (lane >> 2);
    int k = ks * 16 + (lane & 3) + word * 4;
    dst[id] = __uint_as_float(f2tf32(src[(size_t)k * N + n]));
}

// agg = (1 + eps[0]) * x   (layer 0 only; later layers fused into GEMM2 epilogue)
__global__ void init_agg(float* __restrict__ agg, const float* __restrict__ hin,
                         const float* __restrict__ eps_arr, int l) {
    size_t i = (size_t)blockIdx.x * blockDim.x + threadIdx.x;
    if (i < (size_t)NN * D / 4) {
        float s = 1.0f + __ldg(&eps_arr[l]);
        float4 v = ((const float4*)hin)[i];
        v.x *= s; v.y *= s; v.z *= s; v.w *= s;
        ((float4*)agg)[i] = v;
    }
}

__global__ void scatter_edges(float* __restrict__ agg, const float* __restrict__ h,
                              const void* __restrict__ ei) {
    int wid = (int)(((size_t)blockIdx.x * blockDim.x + threadIdx.x) >> 5);
    if (wid >= NE) return;
    int lane = threadIdx.x & 31;
    int is64 = g_is64;
    long long s = load_index(ei, wid, is64);
    long long d = load_index(ei, (long long)NE + wid, is64);
    const float4* hs = (const float4*)(h + (size_t)s * D);
    float*        ad = agg + (size_t)d * D;
    float4 v0 = __ldg(hs + lane);
    float4 v1 = __ldg(hs + 32 + lane);
    red_add_v4(ad + lane * 4,       v0);
    red_add_v4(ad + 128 + lane * 4, v1);
}

__global__ void pool_scatter(float* __restrict__ pool, float* __restrict__ cnt,
                             const float* __restrict__ h, const void* __restrict__ batch) {
    int wid = (int)(((size_t)blockIdx.x * blockDim.x + threadIdx.x) >> 5);
    if (wid >= NN) return;
    int lane = threadIdx.x & 31;
    long long g = load_index(batch, wid, g_is64);
    const float4* hs = (const float4*)(h + (size_t)wid * D);
    float*        pd = pool + (size_t)g * D;
    float4 v0 = __ldg(hs + lane);
    float4 v1 = __ldg(hs + 32 + lane);
    red_add_v4(pd + lane * 4,       v0);
    red_add_v4(pd + 128 + lane * 4, v1);
    if (lane == 0) atomicAdd(&cnt[g], 1.0f);
}

__global__ void zero_pool(float* __restrict__ pool, float* __restrict__ cnt) {
    int i = blockIdx.x * blockDim.x + threadIdx.x;
    if (i < NG * D / 4) ((float4*)pool)[i] = make_float4(0.f, 0.f, 0.f, 0.f);
    if (i < NG) cnt[i] = 0.f;
}

__global__ void normalize_pool(float* __restrict__ pool, const float* __restrict__ cnt) {
    int i = blockIdx.x * blockDim.x + threadIdx.x;
    if (i < NG * D / 4) {
        int g = i >> 6;
        float s = 1.0f / fmaxf(__ldg(&cnt[g]), 1.0f);
        float4 v = ((float4*)pool)[i];
        v.x *= s; v.y *= s; v.z *= s; v.w *= s;
        ((float4*)pool)[i] = v;
    }
}

// ---------------- tf32 mma.sync GEMM ----------------
// C[:, col0:col0+256] = epi(A[M,K] @ W + bias), W pre-permuted tf32 fragment order.
// CTA 128x256, 8 warps as 2(m) x 4(n), warp tile 64x64 of m16n8k8.
// SMEM per stage: A 2048 floats (plane-major frag order) + B 4096 floats (lane-major).
constexpr int SMEM_GEMM = 2 * 6144 * 4;   // 48 KB

template<int EPI, bool WAGG>
__global__ __launch_bounds__(256, 1)
void tgemm(const float* __restrict__ A, const float* __restrict__ Wf,
           const float* __restrict__ bias, float* __restrict__ C,
           int M, int K, int Ntotal,
           const float* __restrict__ bns, const float* __restrict__ bnb,
           float* __restrict__ aggout, const float* __restrict__ eps_arr, int eps_idx)
{
    extern __shared__ float sm[];
    const int tid  = threadIdx.x;
    const int w    = tid >> 5, lane = tid & 31;
    const int wm   = w >> 2,   wn   = w & 3;
    const int row0 = blockIdx.y * 128;
    const int col0 = blockIdx.x * 256;
    const int K16  = K >> 4;

    // --- A staging mapping (thread -> 2 float4 of one row-half) ---
    const int sr   = tid >> 1;          // A tile row 0..127
    const int half = tid & 1;           // cols 0..7 (ks0) or 8..15 (ks1)
    const int mt   = sr >> 4, lr = sr & 15;
    const int fl0  = (lr & 7) * 4;
    // plane-major tile: off = tile*128 + slot*32 + fragLane
    const int aoff0 = (half * 8 + mt) * 128 + (lr >> 3) * 32 + fl0;
    const int aoff1 = aoff0 + 64;       // slot +2
    int arow = row0 + sr; if (arow > M - 1) arow = M - 1;
    const float* Asrc = A + (size_t)arow * K + half * 8;
    const float* Bsrc = Wf + ((size_t)blockIdx.x * K16 << 12);

    float4 acc[4][8];
    #pragma unroll
    for (int i = 0; i < 4; i++)
        #pragma unroll
        for (int j = 0; j < 8; j++) acc[i][j] = make_float4(0.f, 0.f, 0.f, 0.f);

    float4 av0, av1;
    {   // prologue: stage 0
        const float4* p = (const float4*)Asrc;
        av0 = __ldg(p); av1 = __ldg(p + 1);
        float* bb = sm + 2048;
        #pragma unroll
        for (int i2 = 0; i2 < 4; i2++) {
            int c = tid + i2 * 256;
            cp_async16s(smem_u32(bb + c * 4), Bsrc + c * 4);
        }
        cp_commit();
        uint4 u0 = { f2tf32(av0.x), f2tf32(av0.y), f2tf32(av0.z), f2tf32(av0.w) };
        uint4 u1 = { f2tf32(av1.x), f2tf32(av1.y), f2tf32(av1.z), f2tf32(av1.w) };
        *(uint4*)(sm + aoff0) = u0;
        *(uint4*)(sm + aoff1) = u1;
        cp_wait<0>();
        __syncthreads();
    }

    for (int kt = 0; kt < K16; kt++) {
        const int st = kt & 1;
        const bool hn = (kt + 1) < K16;
        if (hn) {
            const float4* p = (const float4*)(Asrc + (size_t)(kt + 1) * 16);
            av0 = __ldg(p); av1 = __ldg(p + 1);
            float* bb = sm + (st ^ 1) * 6144 + 2048;
            const float* src = Bsrc + ((size_t)(kt + 1) << 12);
            #pragma unroll
            for (int i2 = 0; i2 < 4; i2++) {
                int c = tid + i2 * 256;
                cp_async16s(smem_u32(bb + c * 4), src + c * 4);
            }
            cp_commit();
        }
        // ---- compute stage st ----
        const float* base = sm + st * 6144;
        uint4 b[8];
        #pragma unroll
        for (int j = 0; j < 8; j++)
            b[j] = *(const uint4*)(base + 2048 + (wn * 8 + j) * 128 + lane * 4);
        #pragma unroll
        for (int ks = 0; ks < 2; ks++) {
            uint32_t a[4][4];
            #pragma unroll
            for (int i = 0; i < 4; i++)
                #pragma unroll
                for (int s = 0; s < 4; s++)
                    a[i][s] = __float_as_uint(base[(ks * 8 + wm * 4 + i) * 128 + s * 32 + lane]);
            #pragma unroll
            for (int i = 0; i < 4; i++)
                #pragma unroll
                for (int j = 0; j < 8; j++) {
                    uint32_t b0 = ks ? b[j].z : b[j].x;
                    uint32_t b1 = ks ? b[j].w : b[j].y;
                    mma_tf32(acc[i][j], a[i][0], a[i][1], a[i][2], a[i][3], b0, b1);
                }
        }
        if (hn) {
            float* dstA = sm + (st ^ 1) * 6144;
            uint4 u0 = { f2tf32(av0.x), f2tf32(av0.y), f2tf32(av0.z), f2tf32(av0.w) };
            uint4 u1 = { f2tf32(av1.x), f2tf32(av1.y), f2tf32(av1.z), f2tf32(av1.w) };
            *(uint4*)(dstA + aoff0) = u0;
            *(uint4*)(dstA + aoff1) = u1;
            cp_wait<0>();
        }
        __syncthreads();
    }

    // ---------------- epilogue ----------------
    const int g   = lane >> 2, tig = lane & 3;
    const float aggs = WAGG ? (1.0f + __ldg(&eps_arr[eps_idx])) : 0.f;
    #pragma unroll
    for (int j = 0; j < 8; j++) {
        const int cb = col0 + wn * 64 + j * 8 + tig * 2;
        const float2 bi = *(const float2*)(bias + cb);
        float2 bs = make_float2(0.f, 0.f), bt = make_float2(0.f, 0.f);
        if (EPI == 2) { bs = *(const float2*)(bns + cb); bt = *(const float2*)(bnb + cb); }
        #pragma unroll
        for (int i = 0; i < 4; i++) {
            const int r0 = row0 + wm * 64 + i * 16 + g;
            float4 v = acc[i][j];
            float2 lo = make_float2(v.x + bi.x, v.y + bi.y);
            float2 hi = make_float2(v.z + bi.x, v.w + bi.y);
            if (EPI >= 1) {
                lo.x = fmaxf(lo.x, 0.f); lo.y = fmaxf(lo.y, 0.f);
                hi.x = fmaxf(hi.x, 0.f); hi.y = fmaxf(hi.y, 0.f);
            }
            if (EPI == 2) {
                lo.x = fmaf(lo.x, bs.x, bt.x); lo.y = fmaf(lo.y, bs.y, bt.y);
                hi.x = fmaf(hi.x, bs.x, bt.x); hi.y = fmaf(hi.y, bs.y, bt.y);
            }
            if (r0 < M) {
                *(float2*)(C + (size_t)r0 * Ntotal + cb) = lo;
                if (WAGG)
                    *(float2*)(aggout + (size_t)r0 * Ntotal + cb) =
                        make_float2(lo.x * aggs, lo.y * aggs);
            }
            if (r0 + 8 < M) {
                *(float2*)(C + (size_t)(r0 + 8) * Ntotal + cb) = hi;
                if (WAGG)
                    *(float2*)(aggout + (size_t)(r0 + 8) * Ntotal + cb) =
                        make_float2(hi.x * aggs, hi.y * aggs);
            }
        }
    }
}

// ---------------- launcher ----------------
extern "C" void kernel_launch(void* const* d_in, const int* in_sizes, int n_in,
                              void* d_out, int out_size)
{
    const float* x     = (const float*)d_in[0];
    const void*  ei    = d_in[1];
    const void*  batch = d_in[2];
    const float* w1    = (const float*)d_in[3];
    const float* b1    = (const float*)d_in[4];
    const float* w2    = (const float*)d_in[5];
    const float* b2    = (const float*)d_in[6];
    const float* eps   = (const float*)d_in[7];
    const float* bng   = (const float*)d_in[8];
    const float* bnbt  = (const float*)d_in[9];
    const float* bnm   = (const float*)d_in[10];
    const float* bnv   = (const float*)d_in[11];
    const float* wp1   = (const float*)d_in[12];
    const float* bp1   = (const float*)d_in[13];
    const float* wp2   = (const float*)d_in[14];
    const float* bp2   = (const float*)d_in[15];
    float* out = (float*)d_out;

    float *agg, *h, *t, *pool, *cnt, *p1, *bns, *bnb, *wf1, *wf2, *wfp1, *wfp2;
    cudaGetSymbolAddress((void**)&agg,  g_agg);
    cudaGetSymbolAddress((void**)&h,    g_h);
    cudaGetSymbolAddress((void**)&t,    g_t);
    cudaGetSymbolAddress((void**)&pool, g_pool);
    cudaGetSymbolAddress((void**)&cnt,  g_cnt);
    cudaGetSymbolAddress((void**)&p1,   g_p1);
    cudaGetSymbolAddress((void**)&bns,  g_bns);
    cudaGetSymbolAddress((void**)&bnb,  g_bnb);
    cudaGetSymbolAddress((void**)&wf1,  g_wf1);
    cudaGetSymbolAddress((void**)&wf2,  g_wf2);
    cudaGetSymbolAddress((void**)&wfp1, g_wfp1);
    cudaGetSymbolAddress((void**)&wfp2, g_wfp2);

    cudaFuncSetAttribute(tgemm<0, false>, cudaFuncAttributeMaxDynamicSharedMemorySize, SMEM_GEMM);
    cudaFuncSetAttribute(tgemm<1, false>, cudaFuncAttributeMaxDynamicSharedMemorySize, SMEM_GEMM);
    cudaFuncSetAttribute(tgemm<2, false>, cudaFuncAttributeMaxDynamicSharedMemorySize, SMEM_GEMM);
    cudaFuncSetAttribute(tgemm<2, true >, cudaFuncAttributeMaxDynamicSharedMemorySize, SMEM_GEMM);

    detect_idx<<<1, 1>>>((const unsigned int*)ei);
    bn_precompute<<<(5 * D + 255) / 256, 256>>>(bng, bnbt, bnm, bnv);
    // weight prep: tf32 + fragment-order permutation (cheap, once per launch)
    for (int l = 0; l < LGIN; l++) {
        prep_w<<<(D * HID2 + 255) / 256, 256>>>(w1 + (size_t)l * D * HID2,
                                                wf1 + (size_t)l * D * HID2, D, HID2);
        prep_w<<<(HID2 * D + 255) / 256, 256>>>(w2 + (size_t)l * HID2 * D,
                                                wf2 + (size_t)l * HID2 * D, HID2, D);
    }
    prep_w<<<(D * NHID + 255) / 256, 256>>>(wp1, wfp1, D, NHID);
    prep_w<<<(NHID * NOUT + 255) / 256, 256>>>(wp2, wfp2, NHID, NOUT);

    const int bnidx[4] = {0, 0, 1, 2};   // reference's bn-index bug, kept

    const int elem_blocks   = (NN * D / 4 + 255) / 256;
    const int edge_blocks   = (int)(((size_t)NE * 32 + 255) / 256);
    const int node_blocks   = (int)(((size_t)NN * 32 + 255) / 256);
    const int poolv4_blocks = (NG * D / 4 + 255) / 256;
    const int mtiles = (NN + 127) / 128;   // 782

    init_agg<<<elem_blocks, 256>>>(agg, x, eps, 0);

    for (int l = 0; l < LGIN; l++) {
        const float* hin = (l == 0) ? x : h;
        scatter_edges<<<edge_blocks, 256>>>(agg, hin, ei);
        // t = relu(agg @ W1 + b1)   [NN, 512]
        tgemm<1, false><<<dim3(HID2 / 256, mtiles), 256, SMEM_GEMM>>>(
            agg, wf1 + (size_t)l * D * HID2, b1 + (size_t)l * HID2, t,
            NN, D, HID2, nullptr, nullptr, nullptr, nullptr, 0);
        // h = BN(relu(t @ W2 + b2)) [NN, 256]; layers 0-2 also emit agg=(1+eps[l+1])*h
        if (l < LGIN - 1) {
            tgemm<2, true><<<dim3(D / 256, mtiles), 256, SMEM_GEMM>>>(
                t, wf2 + (size_t)l * HID2 * D, b2 + (size_t)l * D, h,
                NN, HID2, D, bns + bnidx[l] * D, bnb + bnidx[l] * D, agg, eps, l + 1);
        } else {
            tgemm<2, false><<<dim3(D / 256, mtiles), 256, SMEM_GEMM>>>(
                t, wf2 + (size_t)l * HID2 * D, b2 + (size_t)l * D, h,
                NN, HID2, D, bns + bnidx[l] * D, bnb + bnidx[l] * D, nullptr, nullptr, 0);
        }
    }

    zero_pool<<<poolv4_blocks, 256>>>(pool, cnt);
    pool_scatter<<<node_blocks, 256>>>(pool, cnt, h, batch);
    normalize_pool<<<poolv4_blocks, 256>>>(pool, cnt);

    tgemm<1, false><<<dim3(NHID / 256, NG / 128), 256, SMEM_GEMM>>>(
        pool, wfp1, bp1, p1, NG, D, NHID, nullptr, nullptr, nullptr, nullptr, 0);
    tgemm<0, false><<<dim3(NOUT / 256, NG / 128), 256, SMEM_GEMM>>>(
        p1, wfp2, bp2, out, NG, NHID, NOUT, nullptr, nullptr, nullptr, nullptr, 0);
}

// round 7
// speedup vs baseline: 3.2426x; 1.2995x over previous
#include <cuda_runtime.h>
#include <cuda_fp16.h>
#include <cstdint>

#define DEV_INLINE __device__ __forceinline__

// ---------------- problem constants ----------------
constexpr int NN   = 100000;
constexpr int NE   = 300000;
constexpr int D    = 256;
constexpr int HID2 = 512;
constexpr int NHID = 512;
constexpr int NOUT = 768;
constexpr int NG   = 4096;
constexpr int LGIN = 4;

// ---------------- scratch (device globals) ----------------
__device__ float  g_agg [(size_t)NN * D];
__device__ float  g_h   [(size_t)NN * D];
__device__ __half g_th  [(size_t)NN * HID2];   // GIN hidden, fp16
__device__ float  g_pool[(size_t)NG * D];
__device__ float  g_cnt [NG];
__device__ float  g_p1  [(size_t)NG * NHID];
__device__ float  g_bns [5 * D];
__device__ float  g_bnb [5 * D];
__device__ int    g_is64;
// fragment-order fp16 weights (uint4 = 8 halves, mma.m16n8k16 B-frag pairs)
__device__ uint4  g_wf1 [(size_t)LGIN * D * HID2 / 8];
__device__ uint4  g_wf2 [(size_t)LGIN * HID2 * D / 8];
__device__ uint4  g_wfp1[(size_t)D * NHID / 8];
__device__ uint4  g_wfp2[(size_t)NHID * NOUT / 8];

// ---------------- PTX helpers ----------------
DEV_INLINE void red_add_v4(float* p, float4 v) {
    asm volatile("red.global.add.v4.f32 [%0], {%1, %2, %3, %4};"
                 :: "l"(p), "f"(v.x), "f"(v.y), "f"(v.z), "f"(v.w) : "memory");
}
DEV_INLINE long long load_index(const void* base, long long i, int is64) {
    if (is64) return ((const long long*)base)[i];
    return (long long)((const int*)base)[i];
}
DEV_INLINE uint32_t smem_u32(const void* p) {
    uint32_t a;
    asm("{ .reg .u64 t; cvta.to.shared.u64 t, %1; cvt.u32.u64 %0, t; }" : "=r"(a) : "l"(p));
    return a;
}
DEV_INLINE void cp_async16s(uint32_t saddr, const void* g) {
    asm volatile("cp.async.cg.shared.global [%0], [%1], 16;" :: "r"(saddr), "l"(g) : "memory");
}
DEV_INLINE void cp_commit() { asm volatile("cp.async.commit_group;" ::: "memory"); }
template<int Nq> DEV_INLINE void cp_wait() { asm volatile("cp.async.wait_group %0;" :: "n"(Nq) : "memory"); }

DEV_INLINE uint32_t pack_h2(float a, float b) {
    __half2 h = __floats2half2_rn(a, b);
    return *(uint32_t*)&h;
}
DEV_INLINE void mma_f16(float4& c, uint32_t a0, uint32_t a1, uint32_t a2, uint32_t a3,
                        uint32_t b0, uint32_t b1) {
    asm volatile(
        "mma.sync.aligned.m16n8k16.row.col.f32.f16.f16.f32 "
        "{%0,%1,%2,%3}, {%4,%5,%6,%7}, {%8,%9}, {%0,%1,%2,%3};"
        : "+f"(c.x), "+f"(c.y), "+f"(c.z), "+f"(c.w)
        : "r"(a0), "r"(a1), "r"(a2), "r"(a3), "r"(b0), "r"(b1));
}

// ---------------- small kernels ----------------
__global__ void detect_idx(const unsigned int* __restrict__ w) {
    unsigned int nz = 0;
    #pragma unroll 1
    for (int k = 0; k < 256; k++) nz |= w[2 * k + 1];
    g_is64 = (nz == 0u) ? 1 : 0;
}

__global__ void bn_precompute(const float* __restrict__ gamma, const float* __restrict__ beta,
                              const float* __restrict__ mean,  const float* __restrict__ var) {
    int i = blockIdx.x * blockDim.x + threadIdx.x;
    if (i < 5 * D) {
        float s = gamma[i] * rsqrtf(var[i] + 1e-5f);
        g_bns[i] = s;
        g_bnb[i] = beta[i] - mean[i] * s;
    }
}

// Pack weight w[K][N] (row-major fp32) into fp16 m16n8k16 fragment order.
// uint4 id = ((nb*K16 + kt)*16 + p)*32 + lane covers n-tile pair (2p, 2p+1).
__global__ void prep_wh(const float* __restrict__ src, uint4* __restrict__ dst, int K, int N) {
    int id = blockIdx.x * blockDim.x + threadIdx.x;
    int K16 = K >> 4;
    int total = (N >> 8) * K16 * 512;
    if (id >= total) return;
    int lane = id & 31;
    int p    = (id >> 5) & 15;
    int blk  = id >> 9;
    int kt   = blk % K16;
    int nb   = blk / K16;
    int g = lane >> 2, tig = lane & 3;
    int c0 = nb * 256 + p * 16 + g;
    int c1 = c0 + 8;
    int k0 = kt * 16 + tig * 2;
    uint32_t u0 = pack_h2(src[(size_t)k0 * N + c0],       src[(size_t)(k0 + 1) * N + c0]);
    uint32_t u1 = pack_h2(src[(size_t)(k0 + 8) * N + c0], src[(size_t)(k0 + 9) * N + c0]);
    uint32_t u2 = pack_h2(src[(size_t)k0 * N + c1],       src[(size_t)(k0 + 1) * N + c1]);
    uint32_t u3 = pack_h2(src[(size_t)(k0 + 8) * N + c1], src[(size_t)(k0 + 9) * N + c1]);
    dst[id] = make_uint4(u0, u1, u2, u3);
}

__global__ void init_agg(float* __restrict__ agg, const float* __restrict__ hin,
                         const float* __restrict__ eps_arr, int l) {
    size_t i = (size_t)blockIdx.x * blockDim.x + threadIdx.x;
    if (i < (size_t)NN * D / 4) {
        float s = 1.0f + __ldg(&eps_arr[l]);
        float4 v = ((const float4*)hin)[i];
        v.x *= s; v.y *= s; v.z *= s; v.w *= s;
        ((float4*)agg)[i] = v;
    }
}

__global__ void scatter_edges(float* __restrict__ agg, const float* __restrict__ h,
                              const void* __restrict__ ei) {
    int wid = (int)(((size_t)blockIdx.x * blockDim.x + threadIdx.x) >> 5);
    if (wid >= NE) return;
    int lane = threadIdx.x & 31;
    int is64 = g_is64;
    long long s = load_index(ei, wid, is64);
    long long d = load_index(ei, (long long)NE + wid, is64);
    const float4* hs = (const float4*)(h + (size_t)s * D);
    float*        ad = agg + (size_t)d * D;
    float4 v0 = __ldg(hs + lane);
    float4 v1 = __ldg(hs + 32 + lane);
    red_add_v4(ad + lane * 4,       v0);
    red_add_v4(ad + 128 + lane * 4, v1);
}

__global__ void pool_scatter(float* __restrict__ pool, float* __restrict__ cnt,
                             const float* __restrict__ h, const void* __restrict__ batch) {
    int wid = (int)(((size_t)blockIdx.x * blockDim.x + threadIdx.x) >> 5);
    if (wid >= NN) return;
    int lane = threadIdx.x & 31;
    long long g = load_index(batch, wid, g_is64);
    const float4* hs = (const float4*)(h + (size_t)wid * D);
    float*        pd = pool + (size_t)g * D;
    float4 v0 = __ldg(hs + lane);
    float4 v1 = __ldg(hs + 32 + lane);
    red_add_v4(pd + lane * 4,       v0);
    red_add_v4(pd + 128 + lane * 4, v1);
    if (lane == 0) atomicAdd(&cnt[g], 1.0f);
}

__global__ void zero_pool(float* __restrict__ pool, float* __restrict__ cnt) {
    int i = blockIdx.x * blockDim.x + threadIdx.x;
    if (i < NG * D / 4) ((float4*)pool)[i] = make_float4(0.f, 0.f, 0.f, 0.f);
    if (i < NG) cnt[i] = 0.f;
}

__global__ void normalize_pool(float* __restrict__ pool, const float* __restrict__ cnt) {
    int i = blockIdx.x * blockDim.x + threadIdx.x;
    if (i < NG * D / 4) {
        int g = i >> 6;
        float s = 1.0f / fmaxf(__ldg(&cnt[g]), 1.0f);
        float4 v = ((float4*)pool)[i];
        v.x *= s; v.y *= s; v.z *= s; v.w *= s;
        ((float4*)pool)[i] = v;
    }
}

// ---------------- fp16 mma.sync GEMM ----------------
// C[:, col0..col0+255] = epi(A[M,K] @ W + bias); W pre-packed fp16 fragment order.
// CTA 128x256, 8 warps as 2(m) x 4(n), warp tile 64x64, m16n8k16, fp32 accum.
// AH: A stored fp16 in gmem; CH: C written fp16.
// SMEM per stage (u32): A [8 mt][4 reg][32 lane] = 1024, B 512 uint4 = 2048.
template<int EPI, bool WAGG, bool AH, bool CH>
__global__ __launch_bounds__(256)
void hgemm(const void* __restrict__ Ain, const uint4* __restrict__ Wf,
           const float* __restrict__ bias, void* __restrict__ Cout,
           int M, int K, int Ntotal,
           const float* __restrict__ bns, const float* __restrict__ bnb,
           float* __restrict__ aggout, const float* __restrict__ eps_arr, int eps_idx)
{
    __shared__ uint32_t smu[2][3072];

    const int tid  = threadIdx.x;
    const int w    = tid >> 5, lane = tid & 31;
    const int wm   = w >> 2,   wn   = w & 3;
    const int row0 = blockIdx.y * 128;
    const int col0 = blockIdx.x * 256;
    const int K16  = K >> 4;

    // producer mapping: thread -> row rr, k-half kk8 (8 halves)
    const int rr   = tid >> 1;
    const int kk8  = tid & 1;
    const int mt   = rr >> 4;
    const int g    = rr & 7;
    const int reg  = ((rr >> 3) & 1) + 2 * kk8;
    const int soff = mt * 128 + reg * 32 + g * 4;
    int rrg = row0 + rr; if (rrg > M - 1) rrg = M - 1;

    const __half* Ah = (const __half*)Ain;
    const float*  Af = (const float*)Ain;
    const uint4*  Bsrc = Wf + (size_t)blockIdx.x * K16 * 512;

    float4 acc[4][8];
    #pragma unroll
    for (int i = 0; i < 4; i++)
        #pragma unroll
        for (int j = 0; j < 8; j++) acc[i][j] = make_float4(0.f, 0.f, 0.f, 0.f);

    uint4  avh;
    float4 av0, av1;

    // prologue: stage 0
    {
        if (AH) avh = *(const uint4*)(Ah + (size_t)rrg * K + kk8 * 8);
        else { const float4* p = (const float4*)(Af + (size_t)rrg * K + kk8 * 8);
               av0 = __ldg(p); av1 = __ldg(p + 1); }
        const uint4* src = Bsrc;
        cp_async16s(smem_u32(&smu[0][1024 + tid * 4]),        src + tid);
        cp_async16s(smem_u32(&smu[0][1024 + 1024 + tid * 4]), src + tid + 256);
        cp_commit();
        uint4 st;
        if (AH) st = avh;
        else st = make_uint4(pack_h2(av0.x, av0.y), pack_h2(av0.z, av0.w),
                             pack_h2(av1.x, av1.y), pack_h2(av1.z, av1.w));
        *(uint4*)(&smu[0][soff]) = st;
        cp_wait<0>();
        __syncthreads();
    }

    for (int kt = 0; kt < K16; kt++) {
        const int st = kt & 1;
        const bool hn = (kt + 1) < K16;
        if (hn) {
            if (AH) avh = *(const uint4*)(Ah + (size_t)rrg * K + (kt + 1) * 16 + kk8 * 8);
            else { const float4* p = (const float4*)(Af + (size_t)rrg * K + (kt + 1) * 16 + kk8 * 8);
                   av0 = __ldg(p); av1 = __ldg(p + 1); }
            const uint4* src = Bsrc + (size_t)(kt + 1) * 512;
            cp_async16s(smem_u32(&smu[st ^ 1][1024 + tid * 4]),        src + tid);
            cp_async16s(smem_u32(&smu[st ^ 1][1024 + 1024 + tid * 4]), src + tid + 256);
            cp_commit();
        }
        // ---- compute stage st ----
        const uint32_t* sA = smu[st];
        const uint32_t* sB = smu[st] + 1024;
        uint4 b[4];
        #pragma unroll
        for (int jp = 0; jp < 4; jp++)
            b[jp] = *(const uint4*)(sB + ((wn * 4 + jp) * 32 + lane) * 4);
        #pragma unroll
        for (int i = 0; i < 4; i++) {
            const uint32_t* ab = sA + (wm * 4 + i) * 128 + lane;
            uint32_t a0 = ab[0], a1 = ab[32], a2 = ab[64], a3 = ab[96];
            #pragma unroll
            for (int jp = 0; jp < 4; jp++) {
                mma_f16(acc[i][jp * 2],     a0, a1, a2, a3, b[jp].x, b[jp].y);
                mma_f16(acc[i][jp * 2 + 1], a0, a1, a2, a3, b[jp].z, b[jp].w);
            }
        }
        if (hn) {
            uint4 stv;
            if (AH) stv = avh;
            else stv = make_uint4(pack_h2(av0.x, av0.y), pack_h2(av0.z, av0.w),
                                  pack_h2(av1.x, av1.y), pack_h2(av1.z, av1.w));
            *(uint4*)(&smu[st ^ 1][soff]) = stv;
            cp_wait<0>();
        }
        __syncthreads();
    }

    // ---------------- epilogue ----------------
    const int eg = lane >> 2, tig = lane & 3;
    const float aggs = WAGG ? (1.0f + __ldg(&eps_arr[eps_idx])) : 0.f;
    float*  Cf = (float*)Cout;
    __half* Ch = (__half*)Cout;
    #pragma unroll
    for (int j = 0; j < 8; j++) {
        const int cb = col0 + wn * 64 + j * 8 + tig * 2;
        const float2 bi = *(const float2*)(bias + cb);
        float2 bs = make_float2(0.f, 0.f), bt = make_float2(0.f, 0.f);
        if (EPI == 2) { bs = *(const float2*)(bns + cb); bt = *(const float2*)(bnb + cb); }
        #pragma unroll
        for (int i = 0; i < 4; i++) {
            const int r0 = row0 + wm * 64 + i * 16 + eg;
            float4 v = acc[i][j];
            float2 lo = make_float2(v.x + bi.x, v.y + bi.y);
            float2 hi = make_float2(v.z + bi.x, v.w + bi.y);
            if (EPI >= 1) {
                lo.x = fmaxf(lo.x, 0.f); lo.y = fmaxf(lo.y, 0.f);
                hi.x = fmaxf(hi.x, 0.f); hi.y = fmaxf(hi.y, 0.f);
            }
            if (EPI == 2) {
                lo.x = fmaf(lo.x, bs.x, bt.x); lo.y = fmaf(lo.y, bs.y, bt.y);
                hi.x = fmaf(hi.x, bs.x, bt.x); hi.y = fmaf(hi.y, bs.y, bt.y);
            }
            if (r0 < M) {
                if (CH) *(__half2*)(Ch + (size_t)r0 * Ntotal + cb) = __floats2half2_rn(lo.x, lo.y);
                else {
                    *(float2*)(Cf + (size_t)r0 * Ntotal + cb) = lo;
                    if (WAGG)
                        *(float2*)(aggout + (size_t)r0 * Ntotal + cb) =
                            make_float2(lo.x * aggs, lo.y * aggs);
                }
            }
            if (r0 + 8 < M) {
                if (CH) *(__half2*)(Ch + (size_t)(r0 + 8) * Ntotal + cb) = __floats2half2_rn(hi.x, hi.y);
                else {
                    *(float2*)(Cf + (size_t)(r0 + 8) * Ntotal + cb) = hi;
                    if (WAGG)
                        *(float2*)(aggout + (size_t)(r0 + 8) * Ntotal + cb) =
                            make_float2(hi.x * aggs, hi.y * aggs);
                }
            }
        }
    }
}

// ---------------- launcher ----------------
extern "C" void kernel_launch(void* const* d_in, const int* in_sizes, int n_in,
                              void* d_out, int out_size)
{
    const float* x     = (const float*)d_in[0];
    const void*  ei    = d_in[1];
    const void*  batch = d_in[2];
    const float* w1    = (const float*)d_in[3];
    const float* b1    = (const float*)d_in[4];
    const float* w2    = (const float*)d_in[5];
    const float* b2    = (const float*)d_in[6];
    const float* eps   = (const float*)d_in[7];
    const float* bng   = (const float*)d_in[8];
    const float* bnbt  = (const float*)d_in[9];
    const float* bnm   = (const float*)d_in[10];
    const float* bnv   = (const float*)d_in[11];
    const float* wp1   = (const float*)d_in[12];
    const float* bp1   = (const float*)d_in[13];
    const float* wp2   = (const float*)d_in[14];
    const float* bp2   = (const float*)d_in[15];
    float* out = (float*)d_out;

    float *agg, *h, *pool, *cnt, *p1, *bns, *bnb;
    __half* th;
    uint4 *wf1, *wf2, *wfp1, *wfp2;
    cudaGetSymbolAddress((void**)&agg,  g_agg);
    cudaGetSymbolAddress((void**)&h,    g_h);
    cudaGetSymbolAddress((void**)&th,   g_th);
    cudaGetSymbolAddress((void**)&pool, g_pool);
    cudaGetSymbolAddress((void**)&cnt,  g_cnt);
    cudaGetSymbolAddress((void**)&p1,   g_p1);
    cudaGetSymbolAddress((void**)&bns,  g_bns);
    cudaGetSymbolAddress((void**)&bnb,  g_bnb);
    cudaGetSymbolAddress((void**)&wf1,  g_wf1);
    cudaGetSymbolAddress((void**)&wf2,  g_wf2);
    cudaGetSymbolAddress((void**)&wfp1, g_wfp1);
    cudaGetSymbolAddress((void**)&wfp2, g_wfp2);

    detect_idx<<<1, 1>>>((const unsigned int*)ei);
    bn_precompute<<<(5 * D + 255) / 256, 256>>>(bng, bnbt, bnm, bnv);
    for (int l = 0; l < LGIN; l++) {
        prep_wh<<<(D * HID2 / 8 + 255) / 256, 256>>>(w1 + (size_t)l * D * HID2,
                                                     wf1 + (size_t)l * D * HID2 / 8, D, HID2);
        prep_wh<<<(HID2 * D / 8 + 255) / 256, 256>>>(w2 + (size_t)l * HID2 * D,
                                                     wf2 + (size_t)l * HID2 * D / 8, HID2, D);
    }
    prep_wh<<<(D * NHID / 8 + 255) / 256, 256>>>(wp1, wfp1, D, NHID);
    prep_wh<<<(NHID * NOUT / 8 + 255) / 256, 256>>>(wp2, wfp2, NHID, NOUT);

    const int bnidx[4] = {0, 0, 1, 2};   // reference's bn-index bug, kept

    const int elem_blocks   = (NN * D / 4 + 255) / 256;
    const int edge_blocks   = (int)(((size_t)NE * 32 + 255) / 256);
    const int node_blocks   = (int)(((size_t)NN * 32 + 255) / 256);
    const int poolv4_blocks = (NG * D / 4 + 255) / 256;
    const int mtiles = (NN + 127) / 128;

    init_agg<<<elem_blocks, 256>>>(agg, x, eps, 0);

    for (int l = 0; l < LGIN; l++) {
        const float* hin = (l == 0) ? x : h;
        scatter_edges<<<edge_blocks, 256>>>(agg, hin, ei);
        // t(fp16) = relu(agg @ W1 + b1)   [NN, 512]
        hgemm<1, false, false, true><<<dim3(HID2 / 256, mtiles), 256>>>(
            agg, wf1 + (size_t)l * D * HID2 / 8, b1 + (size_t)l * HID2, th,
            NN, D, HID2, nullptr, nullptr, nullptr, nullptr, 0);
        // h = BN(relu(t @ W2 + b2)) [NN, 256]; layers 0-2 also emit agg=(1+eps[l+1])*h
        if (l < LGIN - 1) {
            hgemm<2, true, true, false><<<dim3(D / 256, mtiles), 256>>>(
                th, wf2 + (size_t)l * HID2 * D / 8, b2 + (size_t)l * D, h,
                NN, HID2, D, bns + bnidx[l] * D, bnb + bnidx[l] * D, agg, eps, l + 1);
        } else {
            hgemm<2, false, true, false><<<dim3(D / 256, mtiles), 256>>>(
                th, wf2 + (size_t)l * HID2 * D / 8, b2 + (size_t)l * D, h,
                NN, HID2, D, bns + bnidx[l] * D, bnb + bnidx[l] * D, nullptr, nullptr, 0);
        }
    }

    zero_pool<<<poolv4_blocks, 256>>>(pool, cnt);
    pool_scatter<<<node_blocks, 256>>>(pool, cnt, h, batch);
    normalize_pool<<<poolv4_blocks, 256>>>(pool, cnt);

    hgemm<1, false, false, false><<<dim3(NHID / 256, NG / 128), 256>>>(
        pool, wfp1, bp1, p1, NG, D, NHID, nullptr, nullptr, nullptr, nullptr, 0);
    hgemm<0, false, false, false><<<dim3(NOUT / 256, NG / 128), 256>>>(
        p1, wfp2, bp2, out, NG, NHID, NOUT, nullptr, nullptr, nullptr, nullptr, 0);
}